// round 9
// baseline (speedup 1.0000x reference)
#include <cuda_runtime.h>
#include <cstdint>

#define B_SIZE 131072
#define NAG 8
#define HXS 64
#define ENC 128
#define ACTS 5
#define TILE 128
#define NBLK (B_SIZE / TILE)   // 1024

// scratch (device globals: no allocation allowed)
__device__ float g_comm[NAG * HXS];
__device__ float g_pre2[NAG * HXS];
// packed h in per-thread fragment order: per CTA 2048 uint4
// (q=0..3 hi planes, q=4..7 lo planes; index q*256+tid)
__device__ uint4 g_hpk[(size_t)NBLK * NAG * 2048];   // 256 MiB

// ---------------------------------------------------------------------------
// helpers
// ---------------------------------------------------------------------------
__device__ __forceinline__ uint32_t pack_bf16x2(float lo, float hi) {
    uint32_t r;
    asm("cvt.rn.bf16x2.f32 %0, %1, %2;" : "=r"(r) : "f"(hi), "f"(lo));
    return r;
}
__device__ __forceinline__ uint32_t split_pack(float v0, float v1, uint32_t &lop) {
    uint32_t hp = pack_bf16x2(v0, v1);
    float r0 = v0 - __uint_as_float(hp << 16);
    float r1 = v1 - __uint_as_float(hp & 0xffff0000u);
    lop = pack_bf16x2(r0, r1);
    return hp;
}
__device__ __forceinline__ void mma_bf16(float* d, uint32_t a0, uint32_t a1,
                                         uint32_t a2, uint32_t a3,
                                         uint32_t b0, uint32_t b1) {
    asm volatile(
        "mma.sync.aligned.m16n8k16.row.col.f32.bf16.bf16.f32 "
        "{%0,%1,%2,%3}, {%4,%5,%6,%7}, {%8,%9}, {%0,%1,%2,%3};"
        : "+f"(d[0]), "+f"(d[1]), "+f"(d[2]), "+f"(d[3])
        : "r"(a0), "r"(a1), "r"(a2), "r"(a3), "r"(b0), "r"(b1));
}
__device__ __forceinline__ void ldm_x4(uint32_t &r0, uint32_t &r1, uint32_t &r2,
                                       uint32_t &r3, uint32_t addr) {
    asm volatile("ldmatrix.sync.aligned.m8n8.x4.shared.b16 {%0,%1,%2,%3}, [%4];"
                 : "=r"(r0), "=r"(r1), "=r"(r2), "=r"(r3) : "r"(addr));
}
__device__ __forceinline__ void ldm_x4_t(uint32_t &r0, uint32_t &r1, uint32_t &r2,
                                         uint32_t &r3, uint32_t addr) {
    asm volatile("ldmatrix.sync.aligned.m8n8.x4.trans.shared.b16 {%0,%1,%2,%3}, [%4];"
                 : "=r"(r0), "=r"(r1), "=r"(r2), "=r"(r3) : "r"(addr));
}
__device__ __forceinline__ float fast_tanh(float x) {
    float r; asm("tanh.approx.f32 %0, %1;" : "=f"(r) : "f"(x)); return r;
}

__global__ void k_zero() {
    if (threadIdx.x < NAG * HXS) g_comm[threadIdx.x] = 0.f;
}

// ---------------------------------------------------------------------------
// staging: encoder weights stored TRANSPOSED for ldmatrix: sWT[o][k2],
// row stride 68 u32 (64 k2 columns + 4 pad; 272 B rows, 16B-aligned)
// ---------------------------------------------------------------------------
__device__ __forceinline__ void stage_common(
    float* sObs, float* sW1, float* sb1, float* sb2,
    uint32_t* sWTH, uint32_t* sWTL,
    int n, int tid, int b0,
    const float* __restrict__ obs, const float* __restrict__ W1,
    const float* __restrict__ b1, const float* __restrict__ W2,
    const float* __restrict__ b2)
{
    {
        const float4* src = (const float4*)(obs + (size_t)b0 * 16);
        float4* dst = (float4*)sObs;
        dst[tid]       = src[tid];
        dst[tid + 256] = src[tid + 256];
    }
    sW1[tid] = W1[n * 256 + tid];
    if (tid < 128) sb1[tid] = b1[n * 128 + tid];
    if (tid < 64)  sb2[tid] = b2[n * 64 + tid];
    // W2 [128][64] -> packed k-pairs, transposed planes [64 o][68]
    for (int i = tid; i < 64 * 64; i += 256) {
        int k2 = i >> 6, o = i & 63;
        float v0 = W2[n * ENC * HXS + (2 * k2) * 64 + o];
        float v1 = W2[n * ENC * HXS + (2 * k2 + 1) * 64 + o];
        uint32_t lo, hi = split_pack(v0, v1, lo);
        sWTH[o * 68 + k2] = hi;
        sWTL[o * 68 + k2] = lo;
    }
}

// encoder MMA: bf16x3, on-the-fly h1 A-fragments, ldmatrix B-fragments
__device__ __forceinline__ void encoder_mma(
    const float* sObs, const float* sW1, const float* sb1,
    const uint32_t* sWTH, const uint32_t* sWTL,
    int n, int tid, float acc[8][4])
{
    const int w = tid >> 5, lane = tid & 31, g = lane >> 2, t = lane & 3;
    const int r0 = w * 16 + g, r1 = r0 + 8;
    const int mm = lane >> 3, rr = lane & 7;
    const float o00 = sObs[r0 * 16 + 2 * n], o01 = sObs[r0 * 16 + 2 * n + 1];
    const float o10 = sObs[r1 * 16 + 2 * n], o11 = sObs[r1 * 16 + 2 * n + 1];

    // lane base addr: matrix mm -> o-row block (mm>>1)*8, k2 col half (mm&1)*4
    const uint32_t wbH = (uint32_t)__cvta_generic_to_shared(sWTH) +
                         (((mm >> 1) * 8 + rr) * 68 + (mm & 1) * 4) * 4;
    const uint32_t wbL = (uint32_t)__cvta_generic_to_shared(sWTL) +
                         (((mm >> 1) * 8 + rr) * 68 + (mm & 1) * 4) * 4;

#pragma unroll
    for (int nt = 0; nt < 8; nt++)
#pragma unroll
        for (int e = 0; e < 4; e++) acc[nt][e] = 0.f;

#pragma unroll
    for (int kk = 0; kk < 8; kk++) {
        const int c0 = kk * 16 + 2 * t;
        const int c8 = c0 + 8;
        float wA0 = sW1[c0],     wB0 = sW1[128 + c0],     bb0 = sb1[c0];
        float wA1 = sW1[c0 + 1], wB1 = sW1[128 + c0 + 1], bb1 = sb1[c0 + 1];
        float wA8 = sW1[c8],     wB8 = sW1[128 + c8],     bb8 = sb1[c8];
        float wA9 = sW1[c8 + 1], wB9 = sW1[128 + c8 + 1], bb9 = sb1[c8 + 1];

        float v00 = fmaxf(fmaf(o00, wA0, fmaf(o01, wB0, bb0)), 0.f);
        float v01 = fmaxf(fmaf(o00, wA1, fmaf(o01, wB1, bb1)), 0.f);
        float v10 = fmaxf(fmaf(o10, wA0, fmaf(o11, wB0, bb0)), 0.f);
        float v11 = fmaxf(fmaf(o10, wA1, fmaf(o11, wB1, bb1)), 0.f);
        float v08 = fmaxf(fmaf(o00, wA8, fmaf(o01, wB8, bb8)), 0.f);
        float v09 = fmaxf(fmaf(o00, wA9, fmaf(o01, wB9, bb9)), 0.f);
        float v18 = fmaxf(fmaf(o10, wA8, fmaf(o11, wB8, bb8)), 0.f);
        float v19 = fmaxf(fmaf(o10, wA9, fmaf(o11, wB9, bb9)), 0.f);

        uint32_t a0l, a0 = split_pack(v00, v01, a0l);
        uint32_t a1l, a1 = split_pack(v10, v11, a1l);
        uint32_t a2l, a2 = split_pack(v08, v09, a2l);
        uint32_t a3l, a3 = split_pack(v18, v19, a3l);

        const uint32_t kof = kk * 32;   // k2 offset 8*kk (u32), in bytes
#pragma unroll
        for (int jp = 0; jp < 4; jp++) {
            uint32_t bh0a, bh1a, bh0b, bh1b, bl0a, bl1a, bl0b, bl1b;
            ldm_x4(bh0a, bh1a, bh0b, bh1b, wbH + jp * 4352 + kof);
            ldm_x4(bl0a, bl1a, bl0b, bl1b, wbL + jp * 4352 + kof);
            mma_bf16(acc[2 * jp],     a0, a1, a2, a3,     bh0a, bh1a);
            mma_bf16(acc[2 * jp],     a0l, a1l, a2l, a3l, bh0a, bh1a);
            mma_bf16(acc[2 * jp],     a0, a1, a2, a3,     bl0a, bl1a);
            mma_bf16(acc[2 * jp + 1], a0, a1, a2, a3,     bh0b, bh1b);
            mma_bf16(acc[2 * jp + 1], a0l, a1l, a2l, a3l, bh0b, bh1b);
            mma_bf16(acc[2 * jp + 1], a0, a1, a2, a3,     bl0b, bl1b);
        }
    }
}

// ---------------------------------------------------------------------------
// Kernel A: encoder + packed h store + MMA-based comm reduction
// smem (floats): obs 2048 | W1 256 | b1 128 | b2 64 | WTH 4352 | WTL 4352 |
//                HP (u32 [128][36]) 4608 | sC [8][132] 1056 | sR 512 = 17376
// ---------------------------------------------------------------------------
#define C_OBS 0
#define C_W1  2048
#define C_B1  2304
#define C_B2  2432
#define C_WTH 2496
#define C_WTL 6848
#define C_HP  11200
#define C_SC  15808
#define C_SR  16864
#define C_TOT 17376

__global__ __launch_bounds__(256) void k_comm(
    const float* __restrict__ obs, const float* __restrict__ W1,
    const float* __restrict__ b1, const float* __restrict__ W2,
    const float* __restrict__ b2)
{
    extern __shared__ float sm[];
    float* sObs = sm + C_OBS;
    float* sW1  = sm + C_W1;
    float* sb1  = sm + C_B1;
    float* sb2  = sm + C_B2;
    uint32_t* sWTH = (uint32_t*)(sm + C_WTH);
    uint32_t* sWTL = (uint32_t*)(sm + C_WTL);
    uint32_t* sHp = (uint32_t*)(sm + C_HP);   // b16 matrix H[bb][o], 144B rows
    float* sC = sm + C_SC;                    // [8][132]
    float* sR = sm + C_SR;                    // [8][64] block-partial sums

    const int n   = blockIdx.y;
    const int tid = threadIdx.x;
    const int b0  = blockIdx.x * TILE;

    stage_common(sObs, sW1, sb1, sb2, sWTH, sWTL, n, tid, b0, obs, W1, b1, W2, b2);
    sR[tid] = 0.f;
    sR[tid + 256] = 0.f;
    __syncthreads();

    float acc[8][4];
    encoder_mma(sObs, sW1, sb1, sWTH, sWTL, n, tid, acc);

    const int w = tid >> 5, lane = tid & 31, g = lane >> 2, t = lane & 3;
    const int r0 = w * 16 + g, r1 = r0 + 8;

    // epilogue: h = relu(acc + b2); smem b16 tile + global fragment store
    const int ctaL = blockIdx.y * gridDim.x + blockIdx.x;
    uint4* gp = g_hpk + (size_t)ctaL * 2048;
#pragma unroll
    for (int kk = 0; kk < 4; kk++) {
        uint32_t hh[4], ll[4];
#pragma unroll
        for (int s = 0; s < 2; s++) {
            int nt = 2 * kk + s;
            int c0 = nt * 8 + 2 * t;
            float p0 = sb2[c0], p1 = sb2[c0 + 1];
            float v00 = fmaxf(acc[nt][0] + p0, 0.f);
            float v01 = fmaxf(acc[nt][1] + p1, 0.f);
            float v10 = fmaxf(acc[nt][2] + p0, 0.f);
            float v11 = fmaxf(acc[nt][3] + p1, 0.f);
            uint32_t l0, h0 = split_pack(v00, v01, l0);
            uint32_t l1, h1 = split_pack(v10, v11, l1);
            sHp[r0 * 36 + nt * 4 + t] = h0;
            sHp[r1 * 36 + nt * 4 + t] = h1;
            hh[2 * s] = h0; hh[2 * s + 1] = h1;
            ll[2 * s] = l0; ll[2 * s + 1] = l1;
        }
        gp[kk * 256 + tid]       = make_uint4(hh[0], hh[1], hh[2], hh[3]);
        gp[(4 + kk) * 256 + tid] = make_uint4(ll[0], ll[1], ll[2], ll[3]);
    }

    // comm coefficients: coef_i = mask[i][n] / J[i]
    if (tid < 128) {
        float px[NAG], py[NAG];
#pragma unroll
        for (int j = 0; j < NAG; j++) {
            px[j] = sObs[tid * 16 + 2 * j] * 2.0f;       // GRID[0]-1
            py[j] = sObs[tid * 16 + 2 * j + 1] * 6.0f;   // GRID[1]-1
        }
#pragma unroll
        for (int i = 0; i < NAG; i++) {
            float J = 0.f, mn = 0.f;
#pragma unroll
            for (int j = 0; j < NAG; j++) {
                float d = fabsf(px[i] - px[j]) + fabsf(py[i] - py[j]);
                bool msk = (d > 0.f) && (d < 2.0f);
                J += msk ? 1.f : 0.f;
                if (j == n) mn = msk ? 1.f : 0.f;
            }
            if (J <= 0.f) J = 1.f;
            sC[i * 132 + tid] = mn / J;
        }
    }
    __syncthreads();

    // ---- MMA comm reduction: warp w contracts its bb chunk [16w,16w+16) ----
    {
        const int mm = lane >> 3, rr = lane & 7;
        // B = H fragments via ldmatrix.trans (k=bb rows, n=o cols)
        uint32_t hb = (uint32_t)__cvta_generic_to_shared(sHp) +
                      (w * 16 + (mm & 1) * 8 + rr) * 144 + (mm >> 1) * 16;
        // A = coef (bf16 hi/lo split): rows i=g, k=bb
        float2 cA = *(const float2*)(sC + g * 132 + 16 * w + 2 * t);
        float2 cB = *(const float2*)(sC + g * 132 + 16 * w + 8 + 2 * t);
        uint32_t a0l, a0h = split_pack(cA.x, cA.y, a0l);
        uint32_t a2l, a2h = split_pack(cB.x, cB.y, a2l);
#pragma unroll
        for (int jp = 0; jp < 4; jp++) {
            uint32_t b0a, b1a, b0b, b1b;
            ldm_x4_t(b0a, b1a, b0b, b1b, hb + jp * 32);
            float dA[4] = {0.f, 0.f, 0.f, 0.f};
            float dB[4] = {0.f, 0.f, 0.f, 0.f};
            mma_bf16(dA, a0h, 0u, a2h, 0u, b0a, b1a);
            mma_bf16(dA, a0l, 0u, a2l, 0u, b0a, b1a);
            mma_bf16(dB, a0h, 0u, a2h, 0u, b0b, b1b);
            mma_bf16(dB, a0l, 0u, a2l, 0u, b0b, b1b);
            atomicAdd(&sR[g * 64 + (2 * jp) * 8 + 2 * t],         dA[0]);
            atomicAdd(&sR[g * 64 + (2 * jp) * 8 + 2 * t + 1],     dA[1]);
            atomicAdd(&sR[g * 64 + (2 * jp + 1) * 8 + 2 * t],     dB[0]);
            atomicAdd(&sR[g * 64 + (2 * jp + 1) * 8 + 2 * t + 1], dB[1]);
        }
    }
    __syncthreads();
    atomicAdd(&g_comm[tid], sR[tid]);
    atomicAdd(&g_comm[tid + 256], sR[tid + 256]);
}

// pre2[n][o] = bc[n][o] + sum_h comm[n][h] * Wc[n][HX+h][o]
__global__ void k_pre(const float* __restrict__ Wc, const float* __restrict__ bc) {
    const int n = blockIdx.x, o = threadIdx.x;
    float s = bc[n * HXS + o];
#pragma unroll 8
    for (int h = 0; h < HXS; h++)
        s = fmaf(g_comm[n * HXS + h], Wc[n * 2 * HXS * HXS + (HXS + h) * HXS + o], s);
    g_pre2[n * HXS + o] = s;
}

// ---------------------------------------------------------------------------
// Kernel B: decoder only — h fragments from g_hpk, Wc fragments via ldmatrix
// Wc planes transposed [64 o][36] (32 k2 cols + 4 pad) — stride fits here.
// smem (floats): CTH 2304 | CTL 2304 | Wd 320 | pre2 64 | bd 8 = 5000 (20 KB)
// ---------------------------------------------------------------------------
#define D_CTH 0
#define D_CTL 2304
#define D_WD  4608
#define D_P   4928
#define D_BD  4992
#define D_TOT 5000

__global__ __launch_bounds__(256) void k_main(
    const float* __restrict__ Wc, const float* __restrict__ Wd,
    const float* __restrict__ bd, float* __restrict__ out)
{
    extern __shared__ float sm[];
    uint32_t* sCTH = (uint32_t*)(sm + D_CTH);
    uint32_t* sCTL = (uint32_t*)(sm + D_CTL);
    float* sWd = sm + D_WD;
    float* sP  = sm + D_P;
    float* sbd = sm + D_BD;

    const int n   = blockIdx.y;
    const int tid = threadIdx.x;
    const int b0  = blockIdx.x * TILE;

    // Wc lower half [64][64] -> packed k-pairs, transposed planes [64 o][36]
    for (int i = tid; i < 32 * 64; i += 256) {
        int k2 = i >> 6, o = i & 63;
        float v0 = Wc[n * 2 * HXS * HXS + (2 * k2) * 64 + o];
        float v1 = Wc[n * 2 * HXS * HXS + (2 * k2 + 1) * 64 + o];
        uint32_t lo, hi = split_pack(v0, v1, lo);
        sCTH[o * 36 + k2] = hi;
        sCTL[o * 36 + k2] = lo;
    }
    for (int i = tid; i < HXS * ACTS; i += 256) sWd[i] = Wd[n * HXS * ACTS + i];
    if (tid < 64) sP[tid] = g_pre2[n * 64 + tid];
    if (tid < 5)  sbd[tid] = bd[n * 5 + tid];
    __syncthreads();

    const int w = tid >> 5, lane = tid & 31, g = lane >> 2, t = lane & 3;
    const int r0 = w * 16 + g, r1 = r0 + 8;
    const int mm = lane >> 3, rr = lane & 7;
    const int ctaL = blockIdx.y * gridDim.x + blockIdx.x;
    const uint4* gp = g_hpk + (size_t)ctaL * 2048;

    const uint32_t cbH = (uint32_t)__cvta_generic_to_shared(sCTH) +
                         (((mm >> 1) * 8 + rr) * 36 + (mm & 1) * 4) * 4;
    const uint32_t cbL = (uint32_t)__cvta_generic_to_shared(sCTL) +
                         (((mm >> 1) * 8 + rr) * 36 + (mm & 1) * 4) * 4;

    float acc2[8][4];
#pragma unroll
    for (int nt = 0; nt < 8; nt++)
#pragma unroll
        for (int e = 0; e < 4; e++) acc2[nt][e] = 0.f;

#pragma unroll
    for (int kk = 0; kk < 4; kk++) {
        uint4 H = gp[kk * 256 + tid];        // a0..a3 hi (fragment order)
        uint4 L = gp[(4 + kk) * 256 + tid];  // a0..a3 lo
        const uint32_t kof = kk * 32;        // k2 offset 8*kk, bytes
#pragma unroll
        for (int jp = 0; jp < 4; jp++) {
            uint32_t bh0a, bh1a, bh0b, bh1b, bl0a, bl1a, bl0b, bl1b;
            ldm_x4(bh0a, bh1a, bh0b, bh1b, cbH + jp * 2304 + kof);
            ldm_x4(bl0a, bl1a, bl0b, bl1b, cbL + jp * 2304 + kof);
            mma_bf16(acc2[2 * jp],     H.x, H.y, H.z, H.w, bh0a, bh1a);
            mma_bf16(acc2[2 * jp],     L.x, L.y, L.z, L.w, bh0a, bh1a);
            mma_bf16(acc2[2 * jp],     H.x, H.y, H.z, H.w, bl0a, bl1a);
            mma_bf16(acc2[2 * jp + 1], H.x, H.y, H.z, H.w, bh0b, bh1b);
            mma_bf16(acc2[2 * jp + 1], L.x, L.y, L.z, L.w, bh0b, bh1b);
            mma_bf16(acc2[2 * jp + 1], H.x, H.y, H.z, H.w, bl0b, bl1b);
        }
    }

    // h2 = tanh(acc2 + pre2) and q-partials, all in registers
    float q0[ACTS], q1[ACTS];
#pragma unroll
    for (int a = 0; a < ACTS; a++) { q0[a] = 0.f; q1[a] = 0.f; }
#pragma unroll
    for (int nt = 0; nt < 8; nt++) {
        int c0 = nt * 8 + 2 * t;
        float p0 = sP[c0], p1 = sP[c0 + 1];
        float t00 = fast_tanh(acc2[nt][0] + p0);
        float t01 = fast_tanh(acc2[nt][1] + p1);
        float t10 = fast_tanh(acc2[nt][2] + p0);
        float t11 = fast_tanh(acc2[nt][3] + p1);
        const float* wd0 = sWd + c0 * 5;
        const float* wd1 = sWd + (c0 + 1) * 5;
#pragma unroll
        for (int a = 0; a < ACTS; a++) {
            q0[a] = fmaf(t00, wd0[a], fmaf(t01, wd1[a], q0[a]));
            q1[a] = fmaf(t10, wd0[a], fmaf(t11, wd1[a], q1[a]));
        }
    }
#pragma unroll
    for (int a = 0; a < ACTS; a++) {
        q0[a] += __shfl_xor_sync(0xffffffffu, q0[a], 1);
        q0[a] += __shfl_xor_sync(0xffffffffu, q0[a], 2);
        q1[a] += __shfl_xor_sync(0xffffffffu, q1[a], 1);
        q1[a] += __shfl_xor_sync(0xffffffffu, q1[a], 2);
    }
    if (t == 0) {
        float* o0 = out + ((size_t)(b0 + r0) * NAG + n) * ACTS;
        float* o1 = out + ((size_t)(b0 + r1) * NAG + n) * ACTS;
#pragma unroll
        for (int a = 0; a < ACTS; a++) {
            o0[a] = q0[a] + sbd[a];
            o1[a] = q1[a] + sbd[a];
        }
    }
}

extern "C" void kernel_launch(void* const* d_in, const int* in_sizes, int n_in,
                              void* d_out, int out_size)
{
    const float* obs = (const float*)d_in[0];
    const float* W1  = (const float*)d_in[1];
    const float* b1  = (const float*)d_in[2];
    const float* W2  = (const float*)d_in[3];
    const float* b2  = (const float*)d_in[4];
    const float* Wc  = (const float*)d_in[5];
    const float* bc  = (const float*)d_in[6];
    const float* Wd  = (const float*)d_in[7];
    const float* bd  = (const float*)d_in[8];
    float* out = (float*)d_out;

    const int SMEM_C = C_TOT * sizeof(float);   // 69,504 B -> 3 CTAs/SM
    const int SMEM_D = D_TOT * sizeof(float);   // 20,000 B
    cudaFuncSetAttribute(k_comm, cudaFuncAttributeMaxDynamicSharedMemorySize, SMEM_C);
    cudaFuncSetAttribute(k_main, cudaFuncAttributeMaxDynamicSharedMemorySize, SMEM_D);

    k_zero<<<1, 512>>>();
    k_comm<<<dim3(NBLK, NAG), 256, SMEM_C>>>(obs, W1, b1, W2, b2);
    k_pre<<<NAG, HXS>>>(Wc, bc);
    k_main<<<dim3(NBLK, NAG), 256, SMEM_D>>>(Wc, Wd, bd, out);
}

// round 10
// speedup vs baseline: 1.1785x; 1.1785x over previous
#include <cuda_runtime.h>
#include <cstdint>

#define B_SIZE 131072
#define NAG 8
#define HXS 64
#define ENC 128
#define ACTS 5
#define TILE 128
#define NBLK (B_SIZE / TILE)   // 1024

// scratch (device globals: no allocation allowed)
__device__ float g_comm[NAG * HXS];
__device__ float g_pre2[NAG * HXS];
// packed h in per-thread fragment order: per CTA 2048 uint4
// (q=0..3 hi planes, q=4..7 lo planes; index q*256+tid)
__device__ uint4 g_hpk[(size_t)NBLK * NAG * 2048];   // 256 MiB

// ---------------------------------------------------------------------------
// helpers
// ---------------------------------------------------------------------------
__device__ __forceinline__ uint32_t pack_bf16x2(float lo, float hi) {
    uint32_t r;
    asm("cvt.rn.bf16x2.f32 %0, %1, %2;" : "=r"(r) : "f"(hi), "f"(lo));
    return r;
}
__device__ __forceinline__ uint32_t split_pack(float v0, float v1, uint32_t &lop) {
    uint32_t hp = pack_bf16x2(v0, v1);
    float r0 = v0 - __uint_as_float(hp << 16);
    float r1 = v1 - __uint_as_float(hp & 0xffff0000u);
    lop = pack_bf16x2(r0, r1);
    return hp;
}
__device__ __forceinline__ void mma_bf16(float* d, uint32_t a0, uint32_t a1,
                                         uint32_t a2, uint32_t a3,
                                         uint32_t b0, uint32_t b1) {
    asm volatile(
        "mma.sync.aligned.m16n8k16.row.col.f32.bf16.bf16.f32 "
        "{%0,%1,%2,%3}, {%4,%5,%6,%7}, {%8,%9}, {%0,%1,%2,%3};"
        : "+f"(d[0]), "+f"(d[1]), "+f"(d[2]), "+f"(d[3])
        : "r"(a0), "r"(a1), "r"(a2), "r"(a3), "r"(b0), "r"(b1));
}
__device__ __forceinline__ void ldm_x4(uint32_t &r0, uint32_t &r1, uint32_t &r2,
                                       uint32_t &r3, uint32_t addr) {
    asm volatile("ldmatrix.sync.aligned.m8n8.x4.shared.b16 {%0,%1,%2,%3}, [%4];"
                 : "=r"(r0), "=r"(r1), "=r"(r2), "=r"(r3) : "r"(addr));
}
__device__ __forceinline__ void ldm_x4_t(uint32_t &r0, uint32_t &r1, uint32_t &r2,
                                         uint32_t &r3, uint32_t addr) {
    asm volatile("ldmatrix.sync.aligned.m8n8.x4.trans.shared.b16 {%0,%1,%2,%3}, [%4];"
                 : "=r"(r0), "=r"(r1), "=r"(r2), "=r"(r3) : "r"(addr));
}
__device__ __forceinline__ float fast_tanh(float x) {
    float r; asm("tanh.approx.f32 %0, %1;" : "=f"(r) : "f"(x)); return r;
}

__global__ void k_zero() {
    if (threadIdx.x < NAG * HXS) g_comm[threadIdx.x] = 0.f;
}

// ---------------------------------------------------------------------------
// staging: encoder weights stored TRANSPOSED for ldmatrix: sWT[o][k2],
// row stride 68 u32 (64 k2 columns + 4 pad; 272 B rows, 16B-aligned)
// ---------------------------------------------------------------------------
__device__ __forceinline__ void stage_common(
    float* sObs, float* sW1, float* sb1, float* sb2,
    uint32_t* sWTH, uint32_t* sWTL,
    int n, int tid, int b0,
    const float* __restrict__ obs, const float* __restrict__ W1,
    const float* __restrict__ b1, const float* __restrict__ W2,
    const float* __restrict__ b2)
{
    {
        const float4* src = (const float4*)(obs + (size_t)b0 * 16);
        float4* dst = (float4*)sObs;
        dst[tid]       = src[tid];
        dst[tid + 256] = src[tid + 256];
    }
    sW1[tid] = W1[n * 256 + tid];
    if (tid < 128) sb1[tid] = b1[n * 128 + tid];
    if (tid < 64)  sb2[tid] = b2[n * 64 + tid];
    // W2 [128][64] -> packed k-pairs, transposed planes [64 o][68]
    for (int i = tid; i < 64 * 64; i += 256) {
        int k2 = i >> 6, o = i & 63;
        float v0 = W2[n * ENC * HXS + (2 * k2) * 64 + o];
        float v1 = W2[n * ENC * HXS + (2 * k2 + 1) * 64 + o];
        uint32_t lo, hi = split_pack(v0, v1, lo);
        sWTH[o * 68 + k2] = hi;
        sWTL[o * 68 + k2] = lo;
    }
}

// encoder MMA: bf16x3, on-the-fly h1 A-fragments, ldmatrix B-fragments
__device__ __forceinline__ void encoder_mma(
    const float* sObs, const float* sW1, const float* sb1,
    const uint32_t* sWTH, const uint32_t* sWTL,
    int n, int tid, float acc[8][4])
{
    const int w = tid >> 5, lane = tid & 31, g = lane >> 2, t = lane & 3;
    const int r0 = w * 16 + g, r1 = r0 + 8;
    const int mm = lane >> 3, rr = lane & 7;
    const float o00 = sObs[r0 * 16 + 2 * n], o01 = sObs[r0 * 16 + 2 * n + 1];
    const float o10 = sObs[r1 * 16 + 2 * n], o11 = sObs[r1 * 16 + 2 * n + 1];

    // lane base addr: matrix mm -> o-row block (mm>>1)*8, k2 col half (mm&1)*4
    const uint32_t wbH = (uint32_t)__cvta_generic_to_shared(sWTH) +
                         (((mm >> 1) * 8 + rr) * 68 + (mm & 1) * 4) * 4;
    const uint32_t wbL = (uint32_t)__cvta_generic_to_shared(sWTL) +
                         (((mm >> 1) * 8 + rr) * 68 + (mm & 1) * 4) * 4;

#pragma unroll
    for (int nt = 0; nt < 8; nt++)
#pragma unroll
        for (int e = 0; e < 4; e++) acc[nt][e] = 0.f;

#pragma unroll
    for (int kk = 0; kk < 8; kk++) {
        const int c0 = kk * 16 + 2 * t;
        const int c8 = c0 + 8;
        float wA0 = sW1[c0],     wB0 = sW1[128 + c0],     bb0 = sb1[c0];
        float wA1 = sW1[c0 + 1], wB1 = sW1[128 + c0 + 1], bb1 = sb1[c0 + 1];
        float wA8 = sW1[c8],     wB8 = sW1[128 + c8],     bb8 = sb1[c8];
        float wA9 = sW1[c8 + 1], wB9 = sW1[128 + c8 + 1], bb9 = sb1[c8 + 1];

        float v00 = fmaxf(fmaf(o00, wA0, fmaf(o01, wB0, bb0)), 0.f);
        float v01 = fmaxf(fmaf(o00, wA1, fmaf(o01, wB1, bb1)), 0.f);
        float v10 = fmaxf(fmaf(o10, wA0, fmaf(o11, wB0, bb0)), 0.f);
        float v11 = fmaxf(fmaf(o10, wA1, fmaf(o11, wB1, bb1)), 0.f);
        float v08 = fmaxf(fmaf(o00, wA8, fmaf(o01, wB8, bb8)), 0.f);
        float v09 = fmaxf(fmaf(o00, wA9, fmaf(o01, wB9, bb9)), 0.f);
        float v18 = fmaxf(fmaf(o10, wA8, fmaf(o11, wB8, bb8)), 0.f);
        float v19 = fmaxf(fmaf(o10, wA9, fmaf(o11, wB9, bb9)), 0.f);

        uint32_t a0l, a0 = split_pack(v00, v01, a0l);
        uint32_t a1l, a1 = split_pack(v10, v11, a1l);
        uint32_t a2l, a2 = split_pack(v08, v09, a2l);
        uint32_t a3l, a3 = split_pack(v18, v19, a3l);

        const uint32_t kof = kk * 32;   // k2 offset 8*kk (u32), in bytes
#pragma unroll
        for (int jp = 0; jp < 4; jp++) {
            uint32_t bh0a, bh1a, bh0b, bh1b, bl0a, bl1a, bl0b, bl1b;
            ldm_x4(bh0a, bh1a, bh0b, bh1b, wbH + jp * 4352 + kof);
            ldm_x4(bl0a, bl1a, bl0b, bl1b, wbL + jp * 4352 + kof);
            mma_bf16(acc[2 * jp],     a0, a1, a2, a3,     bh0a, bh1a);
            mma_bf16(acc[2 * jp],     a0l, a1l, a2l, a3l, bh0a, bh1a);
            mma_bf16(acc[2 * jp],     a0, a1, a2, a3,     bl0a, bl1a);
            mma_bf16(acc[2 * jp + 1], a0, a1, a2, a3,     bh0b, bh1b);
            mma_bf16(acc[2 * jp + 1], a0l, a1l, a2l, a3l, bh0b, bh1b);
            mma_bf16(acc[2 * jp + 1], a0, a1, a2, a3,     bl0b, bl1b);
        }
    }
}

// ---------------------------------------------------------------------------
// Kernel A: encoder + packed h store + MMA comm reduction (no smem atomics)
// smem (floats): obs 2048 | W1 256 | b1 128 | b2 64 | WTH 4352 | WTL 4352 |
//                HP (u32 [128][36]) 4608 (reused as partials [8][520]) |
//                sC [8][132] 1056  = 16864 floats (67,456 B)
// ---------------------------------------------------------------------------
#define C_OBS 0
#define C_W1  2048
#define C_B1  2304
#define C_B2  2432
#define C_WTH 2496
#define C_WTL 6848
#define C_HP  11200
#define C_SC  15808
#define C_TOT 16864

__global__ __launch_bounds__(256) void k_comm(
    const float* __restrict__ obs, const float* __restrict__ W1,
    const float* __restrict__ b1, const float* __restrict__ W2,
    const float* __restrict__ b2)
{
    extern __shared__ float sm[];
    float* sObs = sm + C_OBS;
    float* sW1  = sm + C_W1;
    float* sb1  = sm + C_B1;
    float* sb2  = sm + C_B2;
    uint32_t* sWTH = (uint32_t*)(sm + C_WTH);
    uint32_t* sWTL = (uint32_t*)(sm + C_WTL);
    uint32_t* sHp = (uint32_t*)(sm + C_HP);   // b16 matrix H[bb][o], 144B rows
    float* sC = sm + C_SC;                    // [8][132]

    const int n   = blockIdx.y;
    const int tid = threadIdx.x;
    const int b0  = blockIdx.x * TILE;

    stage_common(sObs, sW1, sb1, sb2, sWTH, sWTL, n, tid, b0, obs, W1, b1, W2, b2);
    __syncthreads();

    float acc[8][4];
    encoder_mma(sObs, sW1, sb1, sWTH, sWTL, n, tid, acc);

    const int w = tid >> 5, lane = tid & 31, g = lane >> 2, t = lane & 3;
    const int r0 = w * 16 + g, r1 = r0 + 8;

    // epilogue: h = relu(acc + b2); smem b16 tile + global fragment store
    const int ctaL = blockIdx.y * gridDim.x + blockIdx.x;
    uint4* gp = g_hpk + (size_t)ctaL * 2048;
#pragma unroll
    for (int kk = 0; kk < 4; kk++) {
        uint32_t hh[4], ll[4];
#pragma unroll
        for (int s = 0; s < 2; s++) {
            int nt = 2 * kk + s;
            int c0 = nt * 8 + 2 * t;
            float p0 = sb2[c0], p1 = sb2[c0 + 1];
            float v00 = fmaxf(acc[nt][0] + p0, 0.f);
            float v01 = fmaxf(acc[nt][1] + p1, 0.f);
            float v10 = fmaxf(acc[nt][2] + p0, 0.f);
            float v11 = fmaxf(acc[nt][3] + p1, 0.f);
            uint32_t l0, h0 = split_pack(v00, v01, l0);
            uint32_t l1, h1 = split_pack(v10, v11, l1);
            sHp[r0 * 36 + nt * 4 + t] = h0;
            sHp[r1 * 36 + nt * 4 + t] = h1;
            hh[2 * s] = h0; hh[2 * s + 1] = h1;
            ll[2 * s] = l0; ll[2 * s + 1] = l1;
        }
        gp[kk * 256 + tid]       = make_uint4(hh[0], hh[1], hh[2], hh[3]);
        gp[(4 + kk) * 256 + tid] = make_uint4(ll[0], ll[1], ll[2], ll[3]);
    }

    // comm coefficients: coef_i = mask[i][n] / J[i]
    if (tid < 128) {
        float px[NAG], py[NAG];
#pragma unroll
        for (int j = 0; j < NAG; j++) {
            px[j] = sObs[tid * 16 + 2 * j] * 2.0f;       // GRID[0]-1
            py[j] = sObs[tid * 16 + 2 * j + 1] * 6.0f;   // GRID[1]-1
        }
#pragma unroll
        for (int i = 0; i < NAG; i++) {
            float J = 0.f, mn = 0.f;
#pragma unroll
            for (int j = 0; j < NAG; j++) {
                float d = fabsf(px[i] - px[j]) + fabsf(py[i] - py[j]);
                bool msk = (d > 0.f) && (d < 2.0f);
                J += msk ? 1.f : 0.f;
                if (j == n) mn = msk ? 1.f : 0.f;
            }
            if (J <= 0.f) J = 1.f;
            sC[i * 132 + tid] = mn / J;
        }
    }
    __syncthreads();

    // ---- MMA comm reduction: warp w contracts its own bb chunk [16w,16w+16)
    //      results kept in registers (no smem atomics) ----
    float dv[4][4];   // [jp][dA0,dA1,dB0,dB1]
    {
        const int mm = lane >> 3, rr = lane & 7;
        // B = H fragments via ldmatrix.trans (k=bb rows, n=o cols)
        uint32_t hb = (uint32_t)__cvta_generic_to_shared(sHp) +
                      (w * 16 + (mm & 1) * 8 + rr) * 144 + (mm >> 1) * 16;
        // A = coef (bf16 hi/lo split): rows i=g, k=bb
        float2 cA = *(const float2*)(sC + g * 132 + 16 * w + 2 * t);
        float2 cB = *(const float2*)(sC + g * 132 + 16 * w + 8 + 2 * t);
        uint32_t a0l, a0h = split_pack(cA.x, cA.y, a0l);
        uint32_t a2l, a2h = split_pack(cB.x, cB.y, a2l);
#pragma unroll
        for (int jp = 0; jp < 4; jp++) {
            uint32_t b0a, b1a, b0b, b1b;
            ldm_x4_t(b0a, b1a, b0b, b1b, hb + jp * 32);
            float dA[4] = {0.f, 0.f, 0.f, 0.f};
            float dB[4] = {0.f, 0.f, 0.f, 0.f};
            mma_bf16(dA, a0h, 0u, a2h, 0u, b0a, b1a);
            mma_bf16(dA, a0l, 0u, a2l, 0u, b0a, b1a);
            mma_bf16(dB, a0h, 0u, a2h, 0u, b0b, b1b);
            mma_bf16(dB, a0l, 0u, a2l, 0u, b0b, b1b);
            dv[jp][0] = dA[0]; dv[jp][1] = dA[1];
            dv[jp][2] = dB[0]; dv[jp][3] = dB[1];
        }
    }
    __syncthreads();   // all warps done reading sHp (each warp reads own rows,
                       // but partial stores below span other warps' rows)

    // stage per-warp partials into the dead sHp region: [w][i*65 + o]
    {
        float* sPart = sm + C_HP;
#pragma unroll
        for (int jp = 0; jp < 4; jp++) {
            int oA = 16 * jp + 2 * t, oB = oA + 8;
            sPart[w * 520 + g * 65 + oA]     = dv[jp][0];
            sPart[w * 520 + g * 65 + oA + 1] = dv[jp][1];
            sPart[w * 520 + g * 65 + oB]     = dv[jp][2];
            sPart[w * 520 + g * 65 + oB + 1] = dv[jp][3];
        }
    }
    __syncthreads();

    // cross-warp sum: 512 outputs over 256 threads, one global atomic each
    {
        const float* sPart = sm + C_HP;
#pragma unroll
        for (int s = 0; s < 2; s++) {
            int idx = tid + s * 256;
            int i = idx >> 6, o = idx & 63;
            float sum = 0.f;
#pragma unroll
            for (int ww = 0; ww < 8; ww++)
                sum += sPart[ww * 520 + i * 65 + o];
            atomicAdd(&g_comm[idx], sum);
        }
    }
}

// pre2[n][o] = bc[n][o] + sum_h comm[n][h] * Wc[n][HX+h][o]
__global__ void k_pre(const float* __restrict__ Wc, const float* __restrict__ bc) {
    const int n = blockIdx.x, o = threadIdx.x;
    float s = bc[n * HXS + o];
#pragma unroll 8
    for (int h = 0; h < HXS; h++)
        s = fmaf(g_comm[n * HXS + h], Wc[n * 2 * HXS * HXS + (HXS + h) * HXS + o], s);
    g_pre2[n * HXS + o] = s;
}

// ---------------------------------------------------------------------------
// Kernel B: decoder only — h fragments from g_hpk, Wc fragments via ldmatrix
// Wc planes transposed [64 o][36] (32 k2 cols + 4 pad)
// smem (floats): CTH 2304 | CTL 2304 | Wd 320 | pre2 64 | bd 8 = 5000 (20 KB)
// ---------------------------------------------------------------------------
#define D_CTH 0
#define D_CTL 2304
#define D_WD  4608
#define D_P   4928
#define D_BD  4992
#define D_TOT 5000

__global__ __launch_bounds__(256) void k_main(
    const float* __restrict__ Wc, const float* __restrict__ Wd,
    const float* __restrict__ bd, float* __restrict__ out)
{
    extern __shared__ float sm[];
    uint32_t* sCTH = (uint32_t*)(sm + D_CTH);
    uint32_t* sCTL = (uint32_t*)(sm + D_CTL);
    float* sWd = sm + D_WD;
    float* sP  = sm + D_P;
    float* sbd = sm + D_BD;

    const int n   = blockIdx.y;
    const int tid = threadIdx.x;
    const int b0  = blockIdx.x * TILE;

    // Wc lower half [64][64] -> packed k-pairs, transposed planes [64 o][36]
    for (int i = tid; i < 32 * 64; i += 256) {
        int k2 = i >> 6, o = i & 63;
        float v0 = Wc[n * 2 * HXS * HXS + (2 * k2) * 64 + o];
        float v1 = Wc[n * 2 * HXS * HXS + (2 * k2 + 1) * 64 + o];
        uint32_t lo, hi = split_pack(v0, v1, lo);
        sCTH[o * 36 + k2] = hi;
        sCTL[o * 36 + k2] = lo;
    }
    for (int i = tid; i < HXS * ACTS; i += 256) sWd[i] = Wd[n * HXS * ACTS + i];
    if (tid < 64) sP[tid] = g_pre2[n * 64 + tid];
    if (tid < 5)  sbd[tid] = bd[n * 5 + tid];
    __syncthreads();

    const int w = tid >> 5, lane = tid & 31, g = lane >> 2, t = lane & 3;
    const int r0 = w * 16 + g, r1 = r0 + 8;
    const int mm = lane >> 3, rr = lane & 7;
    const int ctaL = blockIdx.y * gridDim.x + blockIdx.x;
    const uint4* gp = g_hpk + (size_t)ctaL * 2048;

    const uint32_t cbH = (uint32_t)__cvta_generic_to_shared(sCTH) +
                         (((mm >> 1) * 8 + rr) * 36 + (mm & 1) * 4) * 4;
    const uint32_t cbL = (uint32_t)__cvta_generic_to_shared(sCTL) +
                         (((mm >> 1) * 8 + rr) * 36 + (mm & 1) * 4) * 4;

    float acc2[8][4];
#pragma unroll
    for (int nt = 0; nt < 8; nt++)
#pragma unroll
        for (int e = 0; e < 4; e++) acc2[nt][e] = 0.f;

#pragma unroll
    for (int kk = 0; kk < 4; kk++) {
        uint4 H = gp[kk * 256 + tid];        // a0..a3 hi (fragment order)
        uint4 L = gp[(4 + kk) * 256 + tid];  // a0..a3 lo
        const uint32_t kof = kk * 32;        // k2 offset 8*kk, bytes
#pragma unroll
        for (int jp = 0; jp < 4; jp++) {
            uint32_t bh0a, bh1a, bh0b, bh1b, bl0a, bl1a, bl0b, bl1b;
            ldm_x4(bh0a, bh1a, bh0b, bh1b, cbH + jp * 2304 + kof);
            ldm_x4(bl0a, bl1a, bl0b, bl1b, cbL + jp * 2304 + kof);
            mma_bf16(acc2[2 * jp],     H.x, H.y, H.z, H.w, bh0a, bh1a);
            mma_bf16(acc2[2 * jp],     L.x, L.y, L.z, L.w, bh0a, bh1a);
            mma_bf16(acc2[2 * jp],     H.x, H.y, H.z, H.w, bl0a, bl1a);
            mma_bf16(acc2[2 * jp + 1], H.x, H.y, H.z, H.w, bh0b, bh1b);
            mma_bf16(acc2[2 * jp + 1], L.x, L.y, L.z, L.w, bh0b, bh1b);
            mma_bf16(acc2[2 * jp + 1], H.x, H.y, H.z, H.w, bl0b, bl1b);
        }
    }

    // h2 = tanh(acc2 + pre2) and q-partials, all in registers
    float q0[ACTS], q1[ACTS];
#pragma unroll
    for (int a = 0; a < ACTS; a++) { q0[a] = 0.f; q1[a] = 0.f; }
#pragma unroll
    for (int nt = 0; nt < 8; nt++) {
        int c0 = nt * 8 + 2 * t;
        float p0 = sP[c0], p1 = sP[c0 + 1];
        float t00 = fast_tanh(acc2[nt][0] + p0);
        float t01 = fast_tanh(acc2[nt][1] + p1);
        float t10 = fast_tanh(acc2[nt][2] + p0);
        float t11 = fast_tanh(acc2[nt][3] + p1);
        const float* wd0 = sWd + c0 * 5;
        const float* wd1 = sWd + (c0 + 1) * 5;
#pragma unroll
        for (int a = 0; a < ACTS; a++) {
            q0[a] = fmaf(t00, wd0[a], fmaf(t01, wd1[a], q0[a]));
            q1[a] = fmaf(t10, wd0[a], fmaf(t11, wd1[a], q1[a]));
        }
    }
#pragma unroll
    for (int a = 0; a < ACTS; a++) {
        q0[a] += __shfl_xor_sync(0xffffffffu, q0[a], 1);
        q0[a] += __shfl_xor_sync(0xffffffffu, q0[a], 2);
        q1[a] += __shfl_xor_sync(0xffffffffu, q1[a], 1);
        q1[a] += __shfl_xor_sync(0xffffffffu, q1[a], 2);
    }
    if (t == 0) {
        float* o0 = out + ((size_t)(b0 + r0) * NAG + n) * ACTS;
        float* o1 = out + ((size_t)(b0 + r1) * NAG + n) * ACTS;
#pragma unroll
        for (int a = 0; a < ACTS; a++) {
            o0[a] = q0[a] + sbd[a];
            o1[a] = q1[a] + sbd[a];
        }
    }
}

extern "C" void kernel_launch(void* const* d_in, const int* in_sizes, int n_in,
                              void* d_out, int out_size)
{
    const float* obs = (const float*)d_in[0];
    const float* W1  = (const float*)d_in[1];
    const float* b1  = (const float*)d_in[2];
    const float* W2  = (const float*)d_in[3];
    const float* b2  = (const float*)d_in[4];
    const float* Wc  = (const float*)d_in[5];
    const float* bc  = (const float*)d_in[6];
    const float* Wd  = (const float*)d_in[7];
    const float* bd  = (const float*)d_in[8];
    float* out = (float*)d_out;

    const int SMEM_C = C_TOT * sizeof(float);   // 67,456 B -> 3 CTAs/SM
    const int SMEM_D = D_TOT * sizeof(float);   // 20,000 B
    cudaFuncSetAttribute(k_comm, cudaFuncAttributeMaxDynamicSharedMemorySize, SMEM_C);
    cudaFuncSetAttribute(k_main, cudaFuncAttributeMaxDynamicSharedMemorySize, SMEM_D);

    k_zero<<<1, 512>>>();
    k_comm<<<dim3(NBLK, NAG), 256, SMEM_C>>>(obs, W1, b1, W2, b2);
    k_pre<<<NAG, HXS>>>(Wc, bc);
    k_main<<<dim3(NBLK, NAG), 256, SMEM_D>>>(Wc, Wd, bd, out);
}

// round 11
// speedup vs baseline: 1.2813x; 1.0872x over previous
#include <cuda_runtime.h>
#include <cstdint>

#define B_SIZE 131072
#define NAG 8
#define HXS 64
#define ENC 128
#define ACTS 5
#define TILE 128
#define NBLK (B_SIZE / TILE)   // 1024

// scratch (device globals: no allocation allowed)
__device__ float g_comm[NAG * HXS];
__device__ float g_pre2[NAG * HXS];
// packed h in per-thread fragment order: per CTA 2048 uint4
// (q=0..3 hi planes, q=4..7 lo planes; index q*256+tid)
__device__ uint4 g_hpk[(size_t)NBLK * NAG * 2048];   // 256 MiB

// ---------------------------------------------------------------------------
// helpers
// ---------------------------------------------------------------------------
__device__ __forceinline__ uint32_t pack_bf16x2(float lo, float hi) {
    uint32_t r;
    asm("cvt.rn.bf16x2.f32 %0, %1, %2;" : "=r"(r) : "f"(hi), "f"(lo));
    return r;
}
__device__ __forceinline__ uint32_t split_pack(float v0, float v1, uint32_t &lop) {
    uint32_t hp = pack_bf16x2(v0, v1);
    float r0 = v0 - __uint_as_float(hp << 16);
    float r1 = v1 - __uint_as_float(hp & 0xffff0000u);
    lop = pack_bf16x2(r0, r1);
    return hp;
}
__device__ __forceinline__ void mma_bf16(float* d, uint32_t a0, uint32_t a1,
                                         uint32_t a2, uint32_t a3,
                                         uint32_t b0, uint32_t b1) {
    asm volatile(
        "mma.sync.aligned.m16n8k16.row.col.f32.bf16.bf16.f32 "
        "{%0,%1,%2,%3}, {%4,%5,%6,%7}, {%8,%9}, {%0,%1,%2,%3};"
        : "+f"(d[0]), "+f"(d[1]), "+f"(d[2]), "+f"(d[3])
        : "r"(a0), "r"(a1), "r"(a2), "r"(a3), "r"(b0), "r"(b1));
}
__device__ __forceinline__ void ldm_x4(uint32_t &r0, uint32_t &r1, uint32_t &r2,
                                       uint32_t &r3, uint32_t addr) {
    asm volatile("ldmatrix.sync.aligned.m8n8.x4.shared.b16 {%0,%1,%2,%3}, [%4];"
                 : "=r"(r0), "=r"(r1), "=r"(r2), "=r"(r3) : "r"(addr));
}
__device__ __forceinline__ void ldm_x4_t(uint32_t &r0, uint32_t &r1, uint32_t &r2,
                                         uint32_t &r3, uint32_t addr) {
    asm volatile("ldmatrix.sync.aligned.m8n8.x4.trans.shared.b16 {%0,%1,%2,%3}, [%4];"
                 : "=r"(r0), "=r"(r1), "=r"(r2), "=r"(r3) : "r"(addr));
}
__device__ __forceinline__ float fast_tanh(float x) {
    float r; asm("tanh.approx.f32 %0, %1;" : "=f"(r) : "f"(x)); return r;
}

__global__ void k_zero() {
    if (threadIdx.x < NAG * HXS) g_comm[threadIdx.x] = 0.f;
}

// ---------------------------------------------------------------------------
// staging: encoder weights stored TRANSPOSED for ldmatrix: sWT[o][k2],
// row stride 68 u32 (64 k2 columns + 4 pad; 272 B rows, 16B-aligned)
// ---------------------------------------------------------------------------
__device__ __forceinline__ void stage_common(
    float* sObs, float* sW1, float* sb1, float* sb2,
    uint32_t* sWTH, uint32_t* sWTL,
    int n, int tid, int b0,
    const float* __restrict__ obs, const float* __restrict__ W1,
    const float* __restrict__ b1, const float* __restrict__ W2,
    const float* __restrict__ b2)
{
    {
        const float4* src = (const float4*)(obs + (size_t)b0 * 16);
        float4* dst = (float4*)sObs;
        dst[tid]       = src[tid];
        dst[tid + 256] = src[tid + 256];
    }
    sW1[tid] = W1[n * 256 + tid];
    if (tid < 128) sb1[tid] = b1[n * 128 + tid];
    if (tid < 64)  sb2[tid] = b2[n * 64 + tid];
    // W2 [128][64] -> packed k-pairs, transposed planes [64 o][68]
    for (int i = tid; i < 64 * 64; i += 256) {
        int k2 = i >> 6, o = i & 63;
        float v0 = W2[n * ENC * HXS + (2 * k2) * 64 + o];
        float v1 = W2[n * ENC * HXS + (2 * k2 + 1) * 64 + o];
        uint32_t lo, hi = split_pack(v0, v1, lo);
        sWTH[o * 68 + k2] = hi;
        sWTL[o * 68 + k2] = lo;
    }
}

// encoder MMA: bf16x3, on-the-fly h1 A-fragments, ldmatrix B-fragments
__device__ __forceinline__ void encoder_mma(
    const float* sObs, const float* sW1, const float* sb1,
    const uint32_t* sWTH, const uint32_t* sWTL,
    int n, int tid, float acc[8][4])
{
    const int w = tid >> 5, lane = tid & 31, g = lane >> 2, t = lane & 3;
    const int r0 = w * 16 + g, r1 = r0 + 8;
    const int mm = lane >> 3, rr = lane & 7;
    const float o00 = sObs[r0 * 16 + 2 * n], o01 = sObs[r0 * 16 + 2 * n + 1];
    const float o10 = sObs[r1 * 16 + 2 * n], o11 = sObs[r1 * 16 + 2 * n + 1];

    // lane base addr: matrix mm -> o-row block (mm>>1)*8, k2 col half (mm&1)*4
    const uint32_t wbH = (uint32_t)__cvta_generic_to_shared(sWTH) +
                         (((mm >> 1) * 8 + rr) * 68 + (mm & 1) * 4) * 4;
    const uint32_t wbL = (uint32_t)__cvta_generic_to_shared(sWTL) +
                         (((mm >> 1) * 8 + rr) * 68 + (mm & 1) * 4) * 4;

#pragma unroll
    for (int nt = 0; nt < 8; nt++)
#pragma unroll
        for (int e = 0; e < 4; e++) acc[nt][e] = 0.f;

#pragma unroll
    for (int kk = 0; kk < 8; kk++) {
        const int c0 = kk * 16 + 2 * t;
        const int c8 = c0 + 8;
        float wA0 = sW1[c0],     wB0 = sW1[128 + c0],     bb0 = sb1[c0];
        float wA1 = sW1[c0 + 1], wB1 = sW1[128 + c0 + 1], bb1 = sb1[c0 + 1];
        float wA8 = sW1[c8],     wB8 = sW1[128 + c8],     bb8 = sb1[c8];
        float wA9 = sW1[c8 + 1], wB9 = sW1[128 + c8 + 1], bb9 = sb1[c8 + 1];

        float v00 = fmaxf(fmaf(o00, wA0, fmaf(o01, wB0, bb0)), 0.f);
        float v01 = fmaxf(fmaf(o00, wA1, fmaf(o01, wB1, bb1)), 0.f);
        float v10 = fmaxf(fmaf(o10, wA0, fmaf(o11, wB0, bb0)), 0.f);
        float v11 = fmaxf(fmaf(o10, wA1, fmaf(o11, wB1, bb1)), 0.f);
        float v08 = fmaxf(fmaf(o00, wA8, fmaf(o01, wB8, bb8)), 0.f);
        float v09 = fmaxf(fmaf(o00, wA9, fmaf(o01, wB9, bb9)), 0.f);
        float v18 = fmaxf(fmaf(o10, wA8, fmaf(o11, wB8, bb8)), 0.f);
        float v19 = fmaxf(fmaf(o10, wA9, fmaf(o11, wB9, bb9)), 0.f);

        uint32_t a0l, a0 = split_pack(v00, v01, a0l);
        uint32_t a1l, a1 = split_pack(v10, v11, a1l);
        uint32_t a2l, a2 = split_pack(v08, v09, a2l);
        uint32_t a3l, a3 = split_pack(v18, v19, a3l);

        const uint32_t kof = kk * 32;   // k2 offset 8*kk (u32), in bytes
#pragma unroll
        for (int jp = 0; jp < 4; jp++) {
            uint32_t bh0a, bh1a, bh0b, bh1b, bl0a, bl1a, bl0b, bl1b;
            ldm_x4(bh0a, bh1a, bh0b, bh1b, wbH + jp * 4352 + kof);
            ldm_x4(bl0a, bl1a, bl0b, bl1b, wbL + jp * 4352 + kof);
            mma_bf16(acc[2 * jp],     a0, a1, a2, a3,     bh0a, bh1a);
            mma_bf16(acc[2 * jp],     a0l, a1l, a2l, a3l, bh0a, bh1a);
            mma_bf16(acc[2 * jp],     a0, a1, a2, a3,     bl0a, bl1a);
            mma_bf16(acc[2 * jp + 1], a0, a1, a2, a3,     bh0b, bh1b);
            mma_bf16(acc[2 * jp + 1], a0l, a1l, a2l, a3l, bh0b, bh1b);
            mma_bf16(acc[2 * jp + 1], a0, a1, a2, a3,     bl0b, bl1b);
        }
    }
}

// ---------------------------------------------------------------------------
// Kernel A: encoder + packed h store + MMA comm reduction.
// sHp (b16 H tile) and the partials buffer ALIAS the dead WTH/WTL region
// after the encoder mma loop (barrier-protected) -> smem 49.0 KB, 4 CTAs/SM.
// smem (floats): obs 2048 | W1 256 | b1 128 | b2 64 | WTH 4352 | WTL 4352 |
//                sC [8][132] 1056  = 12256 floats (49,024 B)
// ---------------------------------------------------------------------------
#define C_OBS 0
#define C_W1  2048
#define C_B1  2304
#define C_B2  2432
#define C_WTH 2496
#define C_WTL 6848
#define C_SC  11200
#define C_TOT 12256
#define C_HP  C_WTH   // alias: H tile [128][36] u32, then partials [8][520] f32

__global__ __launch_bounds__(256, 4) void k_comm(
    const float* __restrict__ obs, const float* __restrict__ W1,
    const float* __restrict__ b1, const float* __restrict__ W2,
    const float* __restrict__ b2)
{
    extern __shared__ float sm[];
    float* sObs = sm + C_OBS;
    float* sW1  = sm + C_W1;
    float* sb1  = sm + C_B1;
    float* sb2  = sm + C_B2;
    uint32_t* sWTH = (uint32_t*)(sm + C_WTH);
    uint32_t* sWTL = (uint32_t*)(sm + C_WTL);
    uint32_t* sHp = (uint32_t*)(sm + C_HP);   // alias (post-encoder only)
    float* sC = sm + C_SC;                    // [8][132]

    const int n   = blockIdx.y;
    const int tid = threadIdx.x;
    const int b0  = blockIdx.x * TILE;

    stage_common(sObs, sW1, sb1, sb2, sWTH, sWTL, n, tid, b0, obs, W1, b1, W2, b2);
    __syncthreads();

    float acc[8][4];
    encoder_mma(sObs, sW1, sb1, sWTH, sWTL, n, tid, acc);
    __syncthreads();   // all warps done reading WTH/WTL before sHp overwrites

    const int w = tid >> 5, lane = tid & 31, g = lane >> 2, t = lane & 3;
    const int r0 = w * 16 + g, r1 = r0 + 8;

    // epilogue: h = relu(acc + b2); smem b16 tile (aliased) + global store
    const int ctaL = blockIdx.y * gridDim.x + blockIdx.x;
    uint4* gp = g_hpk + (size_t)ctaL * 2048;
#pragma unroll
    for (int kk = 0; kk < 4; kk++) {
        uint32_t hh[4], ll[4];
#pragma unroll
        for (int s = 0; s < 2; s++) {
            int nt = 2 * kk + s;
            int c0 = nt * 8 + 2 * t;
            float p0 = sb2[c0], p1 = sb2[c0 + 1];
            float v00 = fmaxf(acc[nt][0] + p0, 0.f);
            float v01 = fmaxf(acc[nt][1] + p1, 0.f);
            float v10 = fmaxf(acc[nt][2] + p0, 0.f);
            float v11 = fmaxf(acc[nt][3] + p1, 0.f);
            uint32_t l0, h0 = split_pack(v00, v01, l0);
            uint32_t l1, h1 = split_pack(v10, v11, l1);
            sHp[r0 * 36 + nt * 4 + t] = h0;
            sHp[r1 * 36 + nt * 4 + t] = h1;
            hh[2 * s] = h0; hh[2 * s + 1] = h1;
            ll[2 * s] = l0; ll[2 * s + 1] = l1;
        }
        gp[kk * 256 + tid]       = make_uint4(hh[0], hh[1], hh[2], hh[3]);
        gp[(4 + kk) * 256 + tid] = make_uint4(ll[0], ll[1], ll[2], ll[3]);
    }

    // comm coefficients: coef_i = mask[i][n] / J[i]
    if (tid < 128) {
        float px[NAG], py[NAG];
#pragma unroll
        for (int j = 0; j < NAG; j++) {
            px[j] = sObs[tid * 16 + 2 * j] * 2.0f;       // GRID[0]-1
            py[j] = sObs[tid * 16 + 2 * j + 1] * 6.0f;   // GRID[1]-1
        }
#pragma unroll
        for (int i = 0; i < NAG; i++) {
            float J = 0.f, mn = 0.f;
#pragma unroll
            for (int j = 0; j < NAG; j++) {
                float d = fabsf(px[i] - px[j]) + fabsf(py[i] - py[j]);
                bool msk = (d > 0.f) && (d < 2.0f);
                J += msk ? 1.f : 0.f;
                if (j == n) mn = msk ? 1.f : 0.f;
            }
            if (J <= 0.f) J = 1.f;
            sC[i * 132 + tid] = mn / J;
        }
    }
    __syncthreads();

    // ---- MMA comm reduction: warp w contracts its own bb chunk [16w,16w+16)
    //      results kept in registers (no smem atomics) ----
    float dv[4][4];   // [jp][dA0,dA1,dB0,dB1]
    {
        const int mm = lane >> 3, rr = lane & 7;
        // B = H fragments via ldmatrix.trans (k=bb rows, n=o cols)
        uint32_t hb = (uint32_t)__cvta_generic_to_shared(sHp) +
                      (w * 16 + (mm & 1) * 8 + rr) * 144 + (mm >> 1) * 16;
        // A = coef (bf16 hi/lo split): rows i=g, k=bb
        float2 cA = *(const float2*)(sC + g * 132 + 16 * w + 2 * t);
        float2 cB = *(const float2*)(sC + g * 132 + 16 * w + 8 + 2 * t);
        uint32_t a0l, a0h = split_pack(cA.x, cA.y, a0l);
        uint32_t a2l, a2h = split_pack(cB.x, cB.y, a2l);
#pragma unroll
        for (int jp = 0; jp < 4; jp++) {
            uint32_t b0a, b1a, b0b, b1b;
            ldm_x4_t(b0a, b1a, b0b, b1b, hb + jp * 32);
            float dA[4] = {0.f, 0.f, 0.f, 0.f};
            float dB[4] = {0.f, 0.f, 0.f, 0.f};
            mma_bf16(dA, a0h, 0u, a2h, 0u, b0a, b1a);
            mma_bf16(dA, a0l, 0u, a2l, 0u, b0a, b1a);
            mma_bf16(dB, a0h, 0u, a2h, 0u, b0b, b1b);
            mma_bf16(dB, a0l, 0u, a2l, 0u, b0b, b1b);
            dv[jp][0] = dA[0]; dv[jp][1] = dA[1];
            dv[jp][2] = dB[0]; dv[jp][3] = dB[1];
        }
    }
    __syncthreads();   // all warps done reading sHp before partials overwrite

    // stage per-warp partials into the same (dead) region: [w][i*65 + o]
    {
        float* sPart = sm + C_HP;
#pragma unroll
        for (int jp = 0; jp < 4; jp++) {
            int oA = 16 * jp + 2 * t, oB = oA + 8;
            sPart[w * 520 + g * 65 + oA]     = dv[jp][0];
            sPart[w * 520 + g * 65 + oA + 1] = dv[jp][1];
            sPart[w * 520 + g * 65 + oB]     = dv[jp][2];
            sPart[w * 520 + g * 65 + oB + 1] = dv[jp][3];
        }
    }
    __syncthreads();

    // cross-warp sum: 512 outputs over 256 threads, one global atomic each
    {
        const float* sPart = sm + C_HP;
#pragma unroll
        for (int s = 0; s < 2; s++) {
            int idx = tid + s * 256;
            int i = idx >> 6, o = idx & 63;
            float sum = 0.f;
#pragma unroll
            for (int ww = 0; ww < 8; ww++)
                sum += sPart[ww * 520 + i * 65 + o];
            atomicAdd(&g_comm[idx], sum);
        }
    }
}

// pre2[n][o] = bc[n][o] + sum_h comm[n][h] * Wc[n][HX+h][o]
__global__ void k_pre(const float* __restrict__ Wc, const float* __restrict__ bc) {
    const int n = blockIdx.x, o = threadIdx.x;
    float s = bc[n * HXS + o];
#pragma unroll 8
    for (int h = 0; h < HXS; h++)
        s = fmaf(g_comm[n * HXS + h], Wc[n * 2 * HXS * HXS + (HXS + h) * HXS + o], s);
    g_pre2[n * HXS + o] = s;
}

// ---------------------------------------------------------------------------
// Kernel B: decoder only — h fragments from g_hpk, Wc fragments via ldmatrix.
// Tile order REVERSED vs k_comm's write order for L2 reuse of g_hpk.
// smem (floats): CTH 2304 | CTL 2304 | Wd 320 | pre2 64 | bd 8 = 5000 (20 KB)
// ---------------------------------------------------------------------------
#define D_CTH 0
#define D_CTL 2304
#define D_WD  4608
#define D_P   4928
#define D_BD  4992
#define D_TOT 5000

__global__ __launch_bounds__(256) void k_main(
    const float* __restrict__ Wc, const float* __restrict__ Wd,
    const float* __restrict__ bd, float* __restrict__ out)
{
    extern __shared__ float sm[];
    uint32_t* sCTH = (uint32_t*)(sm + D_CTH);
    uint32_t* sCTL = (uint32_t*)(sm + D_CTL);
    float* sWd = sm + D_WD;
    float* sP  = sm + D_P;
    float* sbd = sm + D_BD;

    const int tid = threadIdx.x;
    // reversed linear tile id: read most-recently-written g_hpk tiles first
    const int ctaL = NBLK * NAG - 1 - (blockIdx.y * gridDim.x + blockIdx.x);
    const int n    = ctaL / NBLK;
    const int b0   = (ctaL % NBLK) * TILE;

    // Wc lower half [64][64] -> packed k-pairs, transposed planes [64 o][36]
    for (int i = tid; i < 32 * 64; i += 256) {
        int k2 = i >> 6, o = i & 63;
        float v0 = Wc[n * 2 * HXS * HXS + (2 * k2) * 64 + o];
        float v1 = Wc[n * 2 * HXS * HXS + (2 * k2 + 1) * 64 + o];
        uint32_t lo, hi = split_pack(v0, v1, lo);
        sCTH[o * 36 + k2] = hi;
        sCTL[o * 36 + k2] = lo;
    }
    for (int i = tid; i < HXS * ACTS; i += 256) sWd[i] = Wd[n * HXS * ACTS + i];
    if (tid < 64) sP[tid] = g_pre2[n * 64 + tid];
    if (tid < 5)  sbd[tid] = bd[n * 5 + tid];
    __syncthreads();

    const int w = tid >> 5, lane = tid & 31, g = lane >> 2, t = lane & 3;
    const int r0 = w * 16 + g, r1 = r0 + 8;
    const int mm = lane >> 3, rr = lane & 7;
    const uint4* gp = g_hpk + (size_t)ctaL * 2048;

    const uint32_t cbH = (uint32_t)__cvta_generic_to_shared(sCTH) +
                         (((mm >> 1) * 8 + rr) * 36 + (mm & 1) * 4) * 4;
    const uint32_t cbL = (uint32_t)__cvta_generic_to_shared(sCTL) +
                         (((mm >> 1) * 8 + rr) * 36 + (mm & 1) * 4) * 4;

    float acc2[8][4];
#pragma unroll
    for (int nt = 0; nt < 8; nt++)
#pragma unroll
        for (int e = 0; e < 4; e++) acc2[nt][e] = 0.f;

#pragma unroll
    for (int kk = 0; kk < 4; kk++) {
        uint4 H = gp[kk * 256 + tid];        // a0..a3 hi (fragment order)
        uint4 L = gp[(4 + kk) * 256 + tid];  // a0..a3 lo
        const uint32_t kof = kk * 32;        // k2 offset 8*kk, bytes
#pragma unroll
        for (int jp = 0; jp < 4; jp++) {
            uint32_t bh0a, bh1a, bh0b, bh1b, bl0a, bl1a, bl0b, bl1b;
            ldm_x4(bh0a, bh1a, bh0b, bh1b, cbH + jp * 2304 + kof);
            ldm_x4(bl0a, bl1a, bl0b, bl1b, cbL + jp * 2304 + kof);
            mma_bf16(acc2[2 * jp],     H.x, H.y, H.z, H.w, bh0a, bh1a);
            mma_bf16(acc2[2 * jp],     L.x, L.y, L.z, L.w, bh0a, bh1a);
            mma_bf16(acc2[2 * jp],     H.x, H.y, H.z, H.w, bl0a, bl1a);
            mma_bf16(acc2[2 * jp + 1], H.x, H.y, H.z, H.w, bh0b, bh1b);
            mma_bf16(acc2[2 * jp + 1], L.x, L.y, L.z, L.w, bh0b, bh1b);
            mma_bf16(acc2[2 * jp + 1], H.x, H.y, H.z, H.w, bl0b, bl1b);
        }
    }

    // h2 = tanh(acc2 + pre2) and q-partials, all in registers
    float q0[ACTS], q1[ACTS];
#pragma unroll
    for (int a = 0; a < ACTS; a++) { q0[a] = 0.f; q1[a] = 0.f; }
#pragma unroll
    for (int nt = 0; nt < 8; nt++) {
        int c0 = nt * 8 + 2 * t;
        float p0 = sP[c0], p1 = sP[c0 + 1];
        float t00 = fast_tanh(acc2[nt][0] + p0);
        float t01 = fast_tanh(acc2[nt][1] + p1);
        float t10 = fast_tanh(acc2[nt][2] + p0);
        float t11 = fast_tanh(acc2[nt][3] + p1);
        const float* wd0 = sWd + c0 * 5;
        const float* wd1 = sWd + (c0 + 1) * 5;
#pragma unroll
        for (int a = 0; a < ACTS; a++) {
            q0[a] = fmaf(t00, wd0[a], fmaf(t01, wd1[a], q0[a]));
            q1[a] = fmaf(t10, wd0[a], fmaf(t11, wd1[a], q1[a]));
        }
    }
#pragma unroll
    for (int a = 0; a < ACTS; a++) {
        q0[a] += __shfl_xor_sync(0xffffffffu, q0[a], 1);
        q0[a] += __shfl_xor_sync(0xffffffffu, q0[a], 2);
        q1[a] += __shfl_xor_sync(0xffffffffu, q1[a], 1);
        q1[a] += __shfl_xor_sync(0xffffffffu, q1[a], 2);
    }
    if (t == 0) {
        float* o0 = out + ((size_t)(b0 + r0) * NAG + n) * ACTS;
        float* o1 = out + ((size_t)(b0 + r1) * NAG + n) * ACTS;
#pragma unroll
        for (int a = 0; a < ACTS; a++) {
            o0[a] = q0[a] + sbd[a];
            o1[a] = q1[a] + sbd[a];
        }
    }
}

extern "C" void kernel_launch(void* const* d_in, const int* in_sizes, int n_in,
                              void* d_out, int out_size)
{
    const float* obs = (const float*)d_in[0];
    const float* W1  = (const float*)d_in[1];
    const float* b1  = (const float*)d_in[2];
    const float* W2  = (const float*)d_in[3];
    const float* b2  = (const float*)d_in[4];
    const float* Wc  = (const float*)d_in[5];
    const float* bc  = (const float*)d_in[6];
    const float* Wd  = (const float*)d_in[7];
    const float* bd  = (const float*)d_in[8];
    float* out = (float*)d_out;

    const int SMEM_C = C_TOT * sizeof(float);   // 49,024 B -> 4 CTAs/SM
    const int SMEM_D = D_TOT * sizeof(float);   // 20,000 B
    cudaFuncSetAttribute(k_comm, cudaFuncAttributeMaxDynamicSharedMemorySize, SMEM_C);
    cudaFuncSetAttribute(k_main, cudaFuncAttributeMaxDynamicSharedMemorySize, SMEM_D);

    k_zero<<<1, 512>>>();
    k_comm<<<dim3(NBLK, NAG), 256, SMEM_C>>>(obs, W1, b1, W2, b2);
    k_pre<<<NAG, HXS>>>(Wc, bc);
    k_main<<<dim3(NBLK, NAG), 256, SMEM_D>>>(Wc, Wd, bd, out);
}